// round 15
// baseline (speedup 1.0000x reference)
#include <cuda_runtime.h>
#include <cuda_fp16.h>
#include <math.h>
#include <stdint.h>

#define BS 2
#define NQ 10000
#define NV 19560
#define EMBED 256
#define NHEAD 8
#define HDIM 32
#define VSTR 320   // padded halfs per position (640 B: toggles hashed bit 8)

// Scratch (allocation-free rule: __device__ globals)
__device__ __half g_vs[(size_t)BS * NV * VSTR];   // projected value fp16, padded row-major
__device__ float g_off[(size_t)BS * NQ * 256];
__device__ float g_attn[(size_t)BS * NQ * 128];
__device__ float g_q[(size_t)BS * NQ * 256];      // tf32(query + qpos)
__device__ float g_wvt[256 * 256];                // tf32(W_val^T)  [n][k]
__device__ float g_wqt[384 * 256];                // tf32([W_off^T ; W_attn^T])

// ===========================================================================
// helpers
// ===========================================================================
__device__ __forceinline__ uint32_t smem_u32(const void* p) {
    uint32_t a;
    asm("{ .reg .u64 t; cvta.to.shared.u64 t, %1; cvt.u32.u64 %0, t; }"
        : "=r"(a) : "l"(p));
    return a;
}
__device__ __forceinline__ uint32_t f2tf(float f) {
    uint32_t r;
    asm("cvt.rna.tf32.f32 %0, %1;" : "=r"(r) : "f"(f));
    return r;
}

#define CP16(dst, src) \
    asm volatile("cp.async.cg.shared.global [%0], [%1], 16;" \
                 :: "r"(dst), "l"(src))
#define CP_COMMIT() asm volatile("cp.async.commit_group;")
#define CP_WAIT(n)  asm volatile("cp.async.wait_group %0;" :: "n"(n))

__device__ __forceinline__ void mma_tf32(float* c,
                                         uint32_t a0, uint32_t a1, uint32_t a2, uint32_t a3,
                                         uint32_t b0, uint32_t b1) {
    asm volatile(
        "mma.sync.aligned.m16n8k8.row.col.f32.tf32.tf32.f32 "
        "{%0,%1,%2,%3}, {%4,%5,%6,%7}, {%8,%9}, {%0,%1,%2,%3};"
        : "+f"(c[0]), "+f"(c[1]), "+f"(c[2]), "+f"(c[3])
        : "r"(a0), "r"(a1), "r"(a2), "r"(a3), "r"(b0), "r"(b1));
}

// ===========================================================================
// conversion kernels — tf32 rounding hoisted here (bit-identical to in-GEMM cvt)
// ===========================================================================
__global__ void conv_q(const float* __restrict__ query, const float* __restrict__ qpos,
                       float* __restrict__ q, int n4)
{
    const int i = blockIdx.x * blockDim.x + threadIdx.x;
    if (i >= n4) return;
    float4 v = ((const float4*)query)[i];
    float4 u = ((const float4*)qpos)[i];
    v.x = __uint_as_float(f2tf(v.x + u.x));
    v.y = __uint_as_float(f2tf(v.y + u.y));
    v.z = __uint_as_float(f2tf(v.z + u.z));
    v.w = __uint_as_float(f2tf(v.w + u.w));
    ((float4*)q)[i] = v;
}

__global__ void conv_w_t_all(const float* __restrict__ Wv,
                             const float* __restrict__ Wo,
                             const float* __restrict__ Wa,
                             float* __restrict__ vt, float* __restrict__ qt)
{
    const float* W;
    float* T;
    int N;
    if (blockIdx.z == 0)      { W = Wv; T = vt;            N = 256; }
    else if (blockIdx.z == 1) { W = Wo; T = qt;            N = 256; }
    else                      { W = Wa; T = qt + 256*256;  N = 128; }
    if ((int)(blockIdx.x * 32) >= N) return;

    __shared__ float t[32][33];
    const int k0 = blockIdx.y * 32, n0 = blockIdx.x * 32;
    const int tx = threadIdx.x & 31, ty = threadIdx.x >> 5;
#pragma unroll
    for (int j = 0; j < 4; j++)
        t[ty + j * 8][tx] = W[(size_t)(k0 + ty + j * 8) * N + n0 + tx];
    __syncthreads();
#pragma unroll
    for (int j = 0; j < 4; j++) {
        const int n = n0 + ty + j * 8;
        const int k = k0 + tx;
        T[(size_t)n * 256 + k] = __uint_as_float(f2tf(t[tx][ty + j * 8]));
    }
}

// ===========================================================================
// tf32 1-term mma.sync GEMM with cp.async double buffering.
// MODE 1: A needs in-kernel tf32 rounding (raw value input); fp16 padded out.
// MODE 2: A and B pre-rounded; split off/attn epilogue. No cvts in loop.
// ===========================================================================
#define FSTR 36
#define ATILE_B (128 * FSTR * 4)
#define STAGE_B (2 * ATILE_B)
#define SMEM_TOT (2 * STAGE_B)

__device__ __forceinline__ void load_chunk(uint32_t sb,
                                           const float* __restrict__ A,
                                           const float* __restrict__ B,
                                           int m0, int n0, int M, int k0, int tid)
{
#pragma unroll
    for (int i = 0; i < 4; i++) {
        const int idx = tid + i * 256;
        const int row = idx >> 3;
        const int seg = idx & 7;
        int gm = m0 + row;
        if (gm >= M) gm = M - 1;
        const uint32_t doff = (uint32_t)(row * (FSTR * 4) + seg * 16);
        CP16(sb + doff,           A + (size_t)gm * 256 + k0 + seg * 4);
        CP16(sb + ATILE_B + doff, B + (size_t)(n0 + row) * 256 + k0 + seg * 4);
    }
}

template <int MODE>
__global__ __launch_bounds__(256)
void tf32_gemm(const float* __restrict__ A, const float* __restrict__ B,
               const float* __restrict__ bias, const float* __restrict__ bias2,
               __half* __restrict__ Cv,
               float* __restrict__ C, float* __restrict__ C2,
               int M)
{
    extern __shared__ char smem[];
    const uint32_t sbase = smem_u32(smem);
    const int tid = threadIdx.x;
    const int wid = tid >> 5;
    const int lane = tid & 31;
    const int m0 = blockIdx.y * 128;
    const int n0 = blockIdx.x * 128;

    const int wm = wid >> 2;
    const int wn = wid & 3;
    const int g = lane >> 2;
    const int t = lane & 3;

    float acc[4][4][4];
#pragma unroll
    for (int i = 0; i < 4; i++)
#pragma unroll
        for (int j = 0; j < 4; j++)
#pragma unroll
            for (int r = 0; r < 4; r++) acc[i][j][r] = 0.f;

    load_chunk(sbase, A, B, m0, n0, M, 0, tid);
    CP_COMMIT();

    const int NCH = 256 / 32;
#pragma unroll 1
    for (int c = 0; c < NCH; c++) {
        if (c + 1 < NCH) {
            load_chunk(sbase + ((c + 1) & 1) * STAGE_B, A, B, m0, n0, M,
                       (c + 1) * 32, tid);
            CP_COMMIT();
            CP_WAIT(1);
        } else {
            CP_WAIT(0);
        }
        __syncthreads();

        const float* sA = (const float*)(smem + (c & 1) * STAGE_B);
        const float* sB = sA + 128 * FSTR;

#pragma unroll
        for (int ks = 0; ks < 4; ks++) {
            const int kk = ks * 8;
            uint32_t a[4][4], b[4][2];
#pragma unroll
            for (int tm = 0; tm < 4; tm++) {
                const int r = wm * 64 + tm * 16;
                if (MODE == 1) {
                    a[tm][0] = f2tf(sA[(r + g)     * FSTR + kk + t]);
                    a[tm][1] = f2tf(sA[(r + g + 8) * FSTR + kk + t]);
                    a[tm][2] = f2tf(sA[(r + g)     * FSTR + kk + t + 4]);
                    a[tm][3] = f2tf(sA[(r + g + 8) * FSTR + kk + t + 4]);
                } else {
                    a[tm][0] = __float_as_uint(sA[(r + g)     * FSTR + kk + t]);
                    a[tm][1] = __float_as_uint(sA[(r + g + 8) * FSTR + kk + t]);
                    a[tm][2] = __float_as_uint(sA[(r + g)     * FSTR + kk + t + 4]);
                    a[tm][3] = __float_as_uint(sA[(r + g + 8) * FSTR + kk + t + 4]);
                }
            }
#pragma unroll
            for (int tn = 0; tn < 4; tn++) {
                const int n = wn * 32 + tn * 8 + g;
                b[tn][0] = __float_as_uint(sB[n * FSTR + kk + t]);
                b[tn][1] = __float_as_uint(sB[n * FSTR + kk + t + 4]);
            }
#pragma unroll
            for (int tm = 0; tm < 4; tm++)
#pragma unroll
                for (int tn = 0; tn < 4; tn++)
                    mma_tf32(acc[tm][tn],
                             a[tm][0], a[tm][1], a[tm][2], a[tm][3],
                             b[tn][0], b[tn][1]);
        }
        __syncthreads();
    }

#pragma unroll
    for (int tm = 0; tm < 4; tm++) {
#pragma unroll
        for (int half = 0; half < 2; half++) {
            const int gm = m0 + wm * 64 + tm * 16 + g + half * 8;
            if (gm >= M) continue;
#pragma unroll
            for (int tn = 0; tn < 4; tn++) {
                const int gn = n0 + wn * 32 + tn * 8 + t * 2;
                float2 o;
                o.x = acc[tm][tn][half * 2 + 0];
                o.y = acc[tm][tn][half * 2 + 1];
                if (MODE == 1) {
                    float2 bsv = *(const float2*)(bias + gn);
                    o.x += bsv.x; o.y += bsv.y;
                    __half2 hv = __floats2half2_rn(o.x, o.y);
                    *(__half2*)(Cv + (size_t)gm * VSTR + gn) = hv;
                } else {
                    if (gn < 256) {
                        float2 bsv = *(const float2*)(bias + gn);
                        o.x += bsv.x; o.y += bsv.y;
                        *(float2*)(C + (size_t)gm * 256 + gn) = o;
                    } else {
                        float2 bsv = *(const float2*)(bias2 + gn - 256);
                        o.x += bsv.x; o.y += bsv.y;
                        *(float2*)(C2 + (size_t)gm * 128 + gn - 256) = o;
                    }
                }
            }
        }
    }
}

// ---------------------------------------------------------------------------
// Deformable sampling v7 (unchanged): one warp = one (b, q), all 8 heads,
// fp16 value in padded row-major layout (VSTR=320).
// ---------------------------------------------------------------------------
__global__ void sample_kernel(const float* __restrict__ refpts,
                              float* __restrict__ out)
{
    const int gwarp = (blockIdx.x * blockDim.x + threadIdx.x) >> 5;
    const int lane = threadIdx.x & 31;
    if (gwarp >= BS * NQ) return;

    const int bq = gwarp;
    const int b  = bq / NQ;
    const int h  = lane >> 2;
    const int pt = lane & 3;
    const unsigned FULL = 0xFFFFFFFFu;

    float a[4];
#pragma unroll
    for (int lv = 0; lv < 4; lv++)
        a[lv] = g_attn[(size_t)bq * 128 + h * 16 + lv * 4 + pt];

    float amax = fmaxf(fmaxf(a[0], a[1]), fmaxf(a[2], a[3]));
    amax = fmaxf(amax, __shfl_xor_sync(FULL, amax, 1));
    amax = fmaxf(amax, __shfl_xor_sync(FULL, amax, 2));
    float wgt[4];
    float es = 0.f;
#pragma unroll
    for (int lv = 0; lv < 4; lv++) { wgt[lv] = __expf(a[lv] - amax); es += wgt[lv]; }
    es += __shfl_xor_sync(FULL, es, 1);
    es += __shfl_xor_sync(FULL, es, 2);
    const float inv = 1.f / es;
#pragma unroll
    for (int lv = 0; lv < 4; lv++) wgt[lv] *= inv;

    const float LW[4] = {160.f, 80.f, 40.f, 20.f};
    const float LH[4] = {92.f, 46.f, 23.f, 12.f};
    const float rx = refpts[(size_t)bq * 8 + pt * 2 + 0];
    const float ry = refpts[(size_t)bq * 8 + pt * 2 + 1];
    float x[4], y[4];
#pragma unroll
    for (int lv = 0; lv < 4; lv++) {
        const float offx = g_off[(size_t)bq * 256 + h * 32 + lv * 8 + pt * 2 + 0];
        const float offy = g_off[(size_t)bq * 256 + h * 32 + lv * 8 + pt * 2 + 1];
        x[lv] = fmaf(rx + offx / LW[lv], LW[lv], -0.5f);
        y[lv] = fmaf(ry + offy / LH[lv], LH[lv], -0.5f);
    }

    const int HH[4] = {92, 46, 23, 12};
    const int WW[4] = {160, 80, 40, 20};
    const int ST[4] = {0, 14720, 18400, 19320};

    const uint4* __restrict__ vp =
        (const uint4*)g_vs + (size_t)b * NV * (VSTR / 8) + lane;

    float2 a0 = {0.f, 0.f}, a1 = {0.f, 0.f}, a2 = {0.f, 0.f}, a3 = {0.f, 0.f};
    const int src_base = lane & 28;

#pragma unroll
    for (int p = 0; p < 16; p++) {
        const int lv = p >> 2;
        const int pp = p & 3;
        const int src = src_base | pp;
        const float xp = __shfl_sync(FULL, x[lv], src);
        const float yp = __shfl_sync(FULL, y[lv], src);
        const float wp = __shfl_sync(FULL, wgt[lv], src);
        const int Hl = HH[lv], Wl = WW[lv], base = ST[lv];

        const float x0f = floorf(xp), y0f = floorf(yp);
        const float wx1r = xp - x0f;
        const float wy1r = yp - y0f;
        const int x0 = (int)x0f, y0 = (int)y0f;

        const bool vx0 = (unsigned)x0 < (unsigned)Wl;
        const bool vx1 = (unsigned)(x0 + 1) < (unsigned)Wl;
        const bool vy0 = (unsigned)y0 < (unsigned)Hl;
        const bool vy1 = (unsigned)(y0 + 1) < (unsigned)Hl;

        const float wy0 = vy0 ? (1.f - wy1r) * wp : 0.f;
        const float wy1 = vy1 ? wy1r * wp : 0.f;
        const float wxa = vx0 ? (1.f - wx1r) : 0.f;
        const float wxb = vx1 ? wx1r : 0.f;

        const int x0c = min(max(x0, 0), Wl - 1);
        const int x1c = min(max(x0 + 1, 0), Wl - 1);
        const int y0c = min(max(y0, 0), Hl - 1);
        const int y1c = min(max(y0 + 1, 0), Hl - 1);

        const int r0 = (base + y0c * Wl) * (VSTR / 8);
        const int r1 = (base + y1c * Wl) * (VSTR / 8);

#pragma unroll
        for (int cn = 0; cn < 4; cn++) {
            const int idx = (cn < 2 ? r0 : r1) + ((cn & 1) ? x1c : x0c) * (VSTR / 8);
            const float cw = (cn == 0 ? wy0 * wxa : cn == 1 ? wy0 * wxb
                              : cn == 2 ? wy1 * wxa : wy1 * wxb);
            const uint4 u = __ldg(vp + idx);
            const float2 f0 = __half22float2(*(const __half2*)&u.x);
            const float2 f1 = __half22float2(*(const __half2*)&u.y);
            const float2 f2 = __half22float2(*(const __half2*)&u.z);
            const float2 f3 = __half22float2(*(const __half2*)&u.w);
            a0.x = fmaf(f0.x, cw, a0.x); a0.y = fmaf(f0.y, cw, a0.y);
            a1.x = fmaf(f1.x, cw, a1.x); a1.y = fmaf(f1.y, cw, a1.y);
            a2.x = fmaf(f2.x, cw, a2.x); a2.y = fmaf(f2.y, cw, a2.y);
            a3.x = fmaf(f3.x, cw, a3.x); a3.y = fmaf(f3.y, cw, a3.y);
        }
    }

    float* op = out + (size_t)bq * EMBED + lane * 8;
    *(float4*)(op)     = make_float4(a0.x, a0.y, a1.x, a1.y);
    *(float4*)(op + 4) = make_float4(a2.x, a2.y, a3.x, a3.y);
}

// ---------------------------------------------------------------------------
extern "C" void kernel_launch(void* const* d_in, const int* in_sizes, int n_in,
                              void* d_out, int out_size)
{
    const float* query   = (const float*)d_in[0];
    const float* value   = (const float*)d_in[1];
    const float* qpos    = (const float*)d_in[2];
    const float* refpts  = (const float*)d_in[3];
    const float* W_val   = (const float*)d_in[4];
    const float* b_val   = (const float*)d_in[5];
    const float* W_off   = (const float*)d_in[6];
    const float* b_off   = (const float*)d_in[7];
    const float* W_attn  = (const float*)d_in[8];
    const float* b_attn  = (const float*)d_in[9];
    float* out = (float*)d_out;

    __half* pvs;
    float *poff, *pattn, *pq, *pwvt, *pwqt;
    cudaGetSymbolAddress((void**)&pvs, g_vs);
    cudaGetSymbolAddress((void**)&poff, g_off);
    cudaGetSymbolAddress((void**)&pattn, g_attn);
    cudaGetSymbolAddress((void**)&pq, g_q);
    cudaGetSymbolAddress((void**)&pwvt, g_wvt);
    cudaGetSymbolAddress((void**)&pwqt, g_wqt);

    const int Mv = BS * NV;      // 39120
    const int Mq = BS * NQ;      // 20000

    cudaFuncSetAttribute(tf32_gemm<1>, cudaFuncAttributeMaxDynamicSharedMemorySize,
                         SMEM_TOT);
    cudaFuncSetAttribute(tf32_gemm<2>, cudaFuncAttributeMaxDynamicSharedMemorySize,
                         SMEM_TOT);

    // q = tf32(query + qpos); tf32-rounded weight transposes
    {
        int n4 = Mq * 256 / 4;
        conv_q<<<(n4 + 255) / 256, 256>>>(query, qpos, pq, n4);
    }
    conv_w_t_all<<<dim3(8, 8, 3), 256>>>(W_val, W_off, W_attn, pwvt, pwqt);

    // value projection -> fp16 padded row-major (A = raw value, cvt in-kernel)
    tf32_gemm<1><<<dim3(2, (Mv + 127) / 128), 256, SMEM_TOT>>>(
        value, pwvt, b_val, nullptr, pvs, nullptr, nullptr, Mv);
    // merged offsets + attn logits: N = 384, all operands pre-rounded
    tf32_gemm<2><<<dim3(3, (Mq + 127) / 128), 256, SMEM_TOT>>>(
        pq, pwqt, b_off, b_attn, nullptr, poff, pattn, Mq);

    // sampling + weighted sum (one warp per (b,q))
    {
        const int total_warps = BS * NQ;                 // 20000
        const int warps_per_block = 8;
        const int blocks = (total_warps + warps_per_block - 1) / warps_per_block;
        sample_kernel<<<blocks, warps_per_block * 32>>>(refpts, out);
    }
}

// round 16
// speedup vs baseline: 1.0022x; 1.0022x over previous
#include <cuda_runtime.h>
#include <cuda_fp16.h>
#include <math.h>
#include <stdint.h>

#define BS 2
#define NQ 10000
#define NV 19560
#define EMBED 256
#define NHEAD 8
#define HDIM 32
#define VSTR 320   // padded halfs per position (640 B: toggles hashed bit 8)

// Scratch (allocation-free rule: __device__ globals)
__device__ __half g_vs[(size_t)BS * NV * VSTR];   // projected value fp16, padded row-major
__device__ float g_off[(size_t)BS * NQ * 256];
__device__ float g_attn[(size_t)BS * NQ * 128];
__device__ float g_q[(size_t)BS * NQ * 256];      // tf32(query + qpos)
__device__ float g_wvt[256 * 256];                // tf32(W_val^T)  [n][k]
__device__ float g_wqt[384 * 256];                // tf32([W_off^T ; W_attn^T])

// ===========================================================================
// helpers
// ===========================================================================
__device__ __forceinline__ uint32_t smem_u32(const void* p) {
    uint32_t a;
    asm("{ .reg .u64 t; cvta.to.shared.u64 t, %1; cvt.u32.u64 %0, t; }"
        : "=r"(a) : "l"(p));
    return a;
}
__device__ __forceinline__ uint32_t f2tf(float f) {
    uint32_t r;
    asm("cvt.rna.tf32.f32 %0, %1;" : "=r"(r) : "f"(f));
    return r;
}

#define CP16(dst, src) \
    asm volatile("cp.async.cg.shared.global [%0], [%1], 16;" \
                 :: "r"(dst), "l"(src))
#define CP_COMMIT() asm volatile("cp.async.commit_group;")
#define CP_WAIT(n)  asm volatile("cp.async.wait_group %0;" :: "n"(n))

__device__ __forceinline__ void mma_tf32(float* c,
                                         uint32_t a0, uint32_t a1, uint32_t a2, uint32_t a3,
                                         uint32_t b0, uint32_t b1) {
    asm volatile(
        "mma.sync.aligned.m16n8k8.row.col.f32.tf32.tf32.f32 "
        "{%0,%1,%2,%3}, {%4,%5,%6,%7}, {%8,%9}, {%0,%1,%2,%3};"
        : "+f"(c[0]), "+f"(c[1]), "+f"(c[2]), "+f"(c[3])
        : "r"(a0), "r"(a1), "r"(a2), "r"(a3), "r"(b0), "r"(b1));
}

// ===========================================================================
// conversion kernels — tf32 rounding hoisted here
// ===========================================================================
__global__ void conv_q(const float* __restrict__ query, const float* __restrict__ qpos,
                       float* __restrict__ q, int n4)
{
    const int i = blockIdx.x * blockDim.x + threadIdx.x;
    if (i >= n4) return;
    float4 v = ((const float4*)query)[i];
    float4 u = ((const float4*)qpos)[i];
    v.x = __uint_as_float(f2tf(v.x + u.x));
    v.y = __uint_as_float(f2tf(v.y + u.y));
    v.z = __uint_as_float(f2tf(v.z + u.z));
    v.w = __uint_as_float(f2tf(v.w + u.w));
    ((float4*)q)[i] = v;
}

__global__ void conv_w_t_all(const float* __restrict__ Wv,
                             const float* __restrict__ Wo,
                             const float* __restrict__ Wa,
                             float* __restrict__ vt, float* __restrict__ qt)
{
    const float* W;
    float* T;
    int N;
    if (blockIdx.z == 0)      { W = Wv; T = vt;            N = 256; }
    else if (blockIdx.z == 1) { W = Wo; T = qt;            N = 256; }
    else                      { W = Wa; T = qt + 256*256;  N = 128; }
    if ((int)(blockIdx.x * 32) >= N) return;

    __shared__ float t[32][33];
    const int k0 = blockIdx.y * 32, n0 = blockIdx.x * 32;
    const int tx = threadIdx.x & 31, ty = threadIdx.x >> 5;
#pragma unroll
    for (int j = 0; j < 4; j++)
        t[ty + j * 8][tx] = W[(size_t)(k0 + ty + j * 8) * N + n0 + tx];
    __syncthreads();
#pragma unroll
    for (int j = 0; j < 4; j++) {
        const int n = n0 + ty + j * 8;
        const int k = k0 + tx;
        T[(size_t)n * 256 + k] = __uint_as_float(f2tf(t[tx][ty + j * 8]));
    }
}

// ===========================================================================
// tf32 1-term mma.sync GEMM, 3-stage cp.async pipeline (prefetch distance 2).
// MODE 1: A gets in-kernel tf32 rounding (raw value input); fp16 padded out.
// MODE 2: operands pre-rounded; split off/attn epilogue.
// ===========================================================================
#define FSTR 36
#define ATILE_B (128 * FSTR * 4)                // 18432 B per tile
#define STAGE_B (2 * ATILE_B)                   // A + B per stage = 36864 B
#define NSTAGE 3
#define SMEM_TOT (NSTAGE * STAGE_B)             // 110592 B (2 CTAs = 221 KB/SM)

__device__ __forceinline__ void load_chunk(uint32_t sb,
                                           const float* __restrict__ A,
                                           const float* __restrict__ B,
                                           int m0, int n0, int M, int k0, int tid)
{
#pragma unroll
    for (int i = 0; i < 4; i++) {
        const int idx = tid + i * 256;
        const int row = idx >> 3;
        const int seg = idx & 7;
        int gm = m0 + row;
        if (gm >= M) gm = M - 1;
        const uint32_t doff = (uint32_t)(row * (FSTR * 4) + seg * 16);
        CP16(sb + doff,           A + (size_t)gm * 256 + k0 + seg * 4);
        CP16(sb + ATILE_B + doff, B + (size_t)(n0 + row) * 256 + k0 + seg * 4);
    }
}

template <int MODE>
__global__ __launch_bounds__(256)
void tf32_gemm(const float* __restrict__ A, const float* __restrict__ B,
               const float* __restrict__ bias, const float* __restrict__ bias2,
               __half* __restrict__ Cv,
               float* __restrict__ C, float* __restrict__ C2,
               int M)
{
    extern __shared__ char smem[];
    const uint32_t sbase = smem_u32(smem);
    const int tid = threadIdx.x;
    const int wid = tid >> 5;
    const int lane = tid & 31;
    const int m0 = blockIdx.y * 128;
    const int n0 = blockIdx.x * 128;

    const int wm = wid >> 2;
    const int wn = wid & 3;
    const int g = lane >> 2;
    const int t = lane & 3;

    float acc[4][4][4];
#pragma unroll
    for (int i = 0; i < 4; i++)
#pragma unroll
        for (int j = 0; j < 4; j++)
#pragma unroll
            for (int r = 0; r < 4; r++) acc[i][j][r] = 0.f;

    // prime 2 stages
    load_chunk(sbase + 0 * STAGE_B, A, B, m0, n0, M, 0, tid);
    CP_COMMIT();
    load_chunk(sbase + 1 * STAGE_B, A, B, m0, n0, M, 32, tid);
    CP_COMMIT();

    const int NCH = 256 / 32;
    int buf = 0;
#pragma unroll 1
    for (int c = 0; c < NCH; c++) {
        if (c + 2 < NCH) {
            int pbuf = buf + 2; if (pbuf >= NSTAGE) pbuf -= NSTAGE;
            load_chunk(sbase + pbuf * STAGE_B, A, B, m0, n0, M, (c + 2) * 32, tid);
            CP_COMMIT();
            CP_WAIT(2);
        } else if (c + 1 < NCH) {
            CP_WAIT(1);
        } else {
            CP_WAIT(0);
        }
        __syncthreads();

        const float* sA = (const float*)(smem + buf * STAGE_B);
        const float* sB = sA + 128 * FSTR;

#pragma unroll
        for (int ks = 0; ks < 4; ks++) {
            const int kk = ks * 8;
            uint32_t a[4][4], b[4][2];
#pragma unroll
            for (int tm = 0; tm < 4; tm++) {
                const int r = wm * 64 + tm * 16;
                if (MODE == 1) {
                    a[tm][0] = f2tf(sA[(r + g)     * FSTR + kk + t]);
                    a[tm][1] = f2tf(sA[(r + g + 8) * FSTR + kk + t]);
                    a[tm][2] = f2tf(sA[(r + g)     * FSTR + kk + t + 4]);
                    a[tm][3] = f2tf(sA[(r + g + 8) * FSTR + kk + t + 4]);
                } else {
                    a[tm][0] = __float_as_uint(sA[(r + g)     * FSTR + kk + t]);
                    a[tm][1] = __float_as_uint(sA[(r + g + 8) * FSTR + kk + t]);
                    a[tm][2] = __float_as_uint(sA[(r + g)     * FSTR + kk + t + 4]);
                    a[tm][3] = __float_as_uint(sA[(r + g + 8) * FSTR + kk + t + 4]);
                }
            }
#pragma unroll
            for (int tn = 0; tn < 4; tn++) {
                const int n = wn * 32 + tn * 8 + g;
                b[tn][0] = __float_as_uint(sB[n * FSTR + kk + t]);
                b[tn][1] = __float_as_uint(sB[n * FSTR + kk + t + 4]);
            }
#pragma unroll
            for (int tm = 0; tm < 4; tm++)
#pragma unroll
                for (int tn = 0; tn < 4; tn++)
                    mma_tf32(acc[tm][tn],
                             a[tm][0], a[tm][1], a[tm][2], a[tm][3],
                             b[tn][0], b[tn][1]);
        }
        __syncthreads();

        if (++buf == NSTAGE) buf = 0;
    }

#pragma unroll
    for (int tm = 0; tm < 4; tm++) {
#pragma unroll
        for (int half = 0; half < 2; half++) {
            const int gm = m0 + wm * 64 + tm * 16 + g + half * 8;
            if (gm >= M) continue;
#pragma unroll
            for (int tn = 0; tn < 4; tn++) {
                const int gn = n0 + wn * 32 + tn * 8 + t * 2;
                float2 o;
                o.x = acc[tm][tn][half * 2 + 0];
                o.y = acc[tm][tn][half * 2 + 1];
                if (MODE == 1) {
                    float2 bsv = *(const float2*)(bias + gn);
                    o.x += bsv.x; o.y += bsv.y;
                    __half2 hv = __floats2half2_rn(o.x, o.y);
                    *(__half2*)(Cv + (size_t)gm * VSTR + gn) = hv;
                } else {
                    if (gn < 256) {
                        float2 bsv = *(const float2*)(bias + gn);
                        o.x += bsv.x; o.y += bsv.y;
                        *(float2*)(C + (size_t)gm * 256 + gn) = o;
                    } else {
                        float2 bsv = *(const float2*)(bias2 + gn - 256);
                        o.x += bsv.x; o.y += bsv.y;
                        *(float2*)(C2 + (size_t)gm * 128 + gn - 256) = o;
                    }
                }
            }
        }
    }
}

// ---------------------------------------------------------------------------
// Deformable sampling v7 (unchanged): one warp = one (b, q), all 8 heads,
// fp16 value in padded row-major layout (VSTR=320).
// ---------------------------------------------------------------------------
__global__ void sample_kernel(const float* __restrict__ refpts,
                              float* __restrict__ out)
{
    const int gwarp = (blockIdx.x * blockDim.x + threadIdx.x) >> 5;
    const int lane = threadIdx.x & 31;
    if (gwarp >= BS * NQ) return;

    const int bq = gwarp;
    const int b  = bq / NQ;
    const int h  = lane >> 2;
    const int pt = lane & 3;
    const unsigned FULL = 0xFFFFFFFFu;

    float a[4];
#pragma unroll
    for (int lv = 0; lv < 4; lv++)
        a[lv] = g_attn[(size_t)bq * 128 + h * 16 + lv * 4 + pt];

    float amax = fmaxf(fmaxf(a[0], a[1]), fmaxf(a[2], a[3]));
    amax = fmaxf(amax, __shfl_xor_sync(FULL, amax, 1));
    amax = fmaxf(amax, __shfl_xor_sync(FULL, amax, 2));
    float wgt[4];
    float es = 0.f;
#pragma unroll
    for (int lv = 0; lv < 4; lv++) { wgt[lv] = __expf(a[lv] - amax); es += wgt[lv]; }
    es += __shfl_xor_sync(FULL, es, 1);
    es += __shfl_xor_sync(FULL, es, 2);
    const float inv = 1.f / es;
#pragma unroll
    for (int lv = 0; lv < 4; lv++) wgt[lv] *= inv;

    const float LW[4] = {160.f, 80.f, 40.f, 20.f};
    const float LH[4] = {92.f, 46.f, 23.f, 12.f};
    const float rx = refpts[(size_t)bq * 8 + pt * 2 + 0];
    const float ry = refpts[(size_t)bq * 8 + pt * 2 + 1];
    float x[4], y[4];
#pragma unroll
    for (int lv = 0; lv < 4; lv++) {
        const float offx = g_off[(size_t)bq * 256 + h * 32 + lv * 8 + pt * 2 + 0];
        const float offy = g_off[(size_t)bq * 256 + h * 32 + lv * 8 + pt * 2 + 1];
        x[lv] = fmaf(rx + offx / LW[lv], LW[lv], -0.5f);
        y[lv] = fmaf(ry + offy / LH[lv], LH[lv], -0.5f);
    }

    const int HH[4] = {92, 46, 23, 12};
    const int WW[4] = {160, 80, 40, 20};
    const int ST[4] = {0, 14720, 18400, 19320};

    const uint4* __restrict__ vp =
        (const uint4*)g_vs + (size_t)b * NV * (VSTR / 8) + lane;

    float2 a0 = {0.f, 0.f}, a1 = {0.f, 0.f}, a2 = {0.f, 0.f}, a3 = {0.f, 0.f};
    const int src_base = lane & 28;

#pragma unroll
    for (int p = 0; p < 16; p++) {
        const int lv = p >> 2;
        const int pp = p & 3;
        const int src = src_base | pp;
        const float xp = __shfl_sync(FULL, x[lv], src);
        const float yp = __shfl_sync(FULL, y[lv], src);
        const float wp = __shfl_sync(FULL, wgt[lv], src);
        const int Hl = HH[lv], Wl = WW[lv], base = ST[lv];

        const float x0f = floorf(xp), y0f = floorf(yp);
        const float wx1r = xp - x0f;
        const float wy1r = yp - y0f;
        const int x0 = (int)x0f, y0 = (int)y0f;

        const bool vx0 = (unsigned)x0 < (unsigned)Wl;
        const bool vx1 = (unsigned)(x0 + 1) < (unsigned)Wl;
        const bool vy0 = (unsigned)y0 < (unsigned)Hl;
        const bool vy1 = (unsigned)(y0 + 1) < (unsigned)Hl;

        const float wy0 = vy0 ? (1.f - wy1r) * wp : 0.f;
        const float wy1 = vy1 ? wy1r * wp : 0.f;
        const float wxa = vx0 ? (1.f - wx1r) : 0.f;
        const float wxb = vx1 ? wx1r : 0.f;

        const int x0c = min(max(x0, 0), Wl - 1);
        const int x1c = min(max(x0 + 1, 0), Wl - 1);
        const int y0c = min(max(y0, 0), Hl - 1);
        const int y1c = min(max(y0 + 1, 0), Hl - 1);

        const int r0 = (base + y0c * Wl) * (VSTR / 8);
        const int r1 = (base + y1c * Wl) * (VSTR / 8);

#pragma unroll
        for (int cn = 0; cn < 4; cn++) {
            const int idx = (cn < 2 ? r0 : r1) + ((cn & 1) ? x1c : x0c) * (VSTR / 8);
            const float cw = (cn == 0 ? wy0 * wxa : cn == 1 ? wy0 * wxb
                              : cn == 2 ? wy1 * wxa : wy1 * wxb);
            const uint4 u = __ldg(vp + idx);
            const float2 f0 = __half22float2(*(const __half2*)&u.x);
            const float2 f1 = __half22float2(*(const __half2*)&u.y);
            const float2 f2 = __half22float2(*(const __half2*)&u.z);
            const float2 f3 = __half22float2(*(const __half2*)&u.w);
            a0.x = fmaf(f0.x, cw, a0.x); a0.y = fmaf(f0.y, cw, a0.y);
            a1.x = fmaf(f1.x, cw, a1.x); a1.y = fmaf(f1.y, cw, a1.y);
            a2.x = fmaf(f2.x, cw, a2.x); a2.y = fmaf(f2.y, cw, a2.y);
            a3.x = fmaf(f3.x, cw, a3.x); a3.y = fmaf(f3.y, cw, a3.y);
        }
    }

    float* op = out + (size_t)bq * EMBED + lane * 8;
    *(float4*)(op)     = make_float4(a0.x, a0.y, a1.x, a1.y);
    *(float4*)(op + 4) = make_float4(a2.x, a2.y, a3.x, a3.y);
}

// ---------------------------------------------------------------------------
extern "C" void kernel_launch(void* const* d_in, const int* in_sizes, int n_in,
                              void* d_out, int out_size)
{
    const float* query   = (const float*)d_in[0];
    const float* value   = (const float*)d_in[1];
    const float* qpos    = (const float*)d_in[2];
    const float* refpts  = (const float*)d_in[3];
    const float* W_val   = (const float*)d_in[4];
    const float* b_val   = (const float*)d_in[5];
    const float* W_off   = (const float*)d_in[6];
    const float* b_off   = (const float*)d_in[7];
    const float* W_attn  = (const float*)d_in[8];
    const float* b_attn  = (const float*)d_in[9];
    float* out = (float*)d_out;

    __half* pvs;
    float *poff, *pattn, *pq, *pwvt, *pwqt;
    cudaGetSymbolAddress((void**)&pvs, g_vs);
    cudaGetSymbolAddress((void**)&poff, g_off);
    cudaGetSymbolAddress((void**)&pattn, g_attn);
    cudaGetSymbolAddress((void**)&pq, g_q);
    cudaGetSymbolAddress((void**)&pwvt, g_wvt);
    cudaGetSymbolAddress((void**)&pwqt, g_wqt);

    const int Mv = BS * NV;      // 39120
    const int Mq = BS * NQ;      // 20000

    cudaFuncSetAttribute(tf32_gemm<1>, cudaFuncAttributeMaxDynamicSharedMemorySize,
                         SMEM_TOT);
    cudaFuncSetAttribute(tf32_gemm<2>, cudaFuncAttributeMaxDynamicSharedMemorySize,
                         SMEM_TOT);

    // q = tf32(query + qpos); tf32-rounded weight transposes
    {
        int n4 = Mq * 256 / 4;
        conv_q<<<(n4 + 255) / 256, 256>>>(query, qpos, pq, n4);
    }
    conv_w_t_all<<<dim3(8, 8, 3), 256>>>(W_val, W_off, W_attn, pwvt, pwqt);

    // value projection -> fp16 padded row-major (A = raw value, cvt in-kernel)
    tf32_gemm<1><<<dim3(2, (Mv + 127) / 128), 256, SMEM_TOT>>>(
        value, pwvt, b_val, nullptr, pvs, nullptr, nullptr, Mv);
    // merged offsets + attn logits: N = 384, operands pre-rounded
    tf32_gemm<2><<<dim3(3, (Mq + 127) / 128), 256, SMEM_TOT>>>(
        pq, pwqt, b_off, b_attn, nullptr, poff, pattn, Mq);

    // sampling + weighted sum (one warp per (b,q))
    {
        const int total_warps = BS * NQ;                 // 20000
        const int warps_per_block = 8;
        const int blocks = (total_warps + warps_per_block - 1) / warps_per_block;
        sample_kernel<<<blocks, warps_per_block * 32>>>(refpts, out);
    }
}